// round 11
// baseline (speedup 1.0000x reference)
#include <cuda_runtime.h>
#include <cuda_bf16.h>
#include <cstdint>

// Problem constants
constexpr int Bb = 2;
constexpr int Tt = 2048;
constexpr int DM = 1024;
constexpr int Hh = 16;
constexpr int HD = 64;
constexpr int MROWS = Bb * Tt;   // 4096

// Scratch (no allocation allowed -> __device__ globals)
__device__ __nv_bfloat16 g_x_hi[MROWS * DM];
__device__ __nv_bfloat16 g_x_lo[MROWS * DM];
__device__ __nv_bfloat16 g_w_hi[4 * DM * DM];   // Wq, Wk, Wv, Wo
__device__ __nv_bfloat16 g_w_lo[4 * DM * DM];
__device__ __nv_bfloat16 g_q_hi[MROWS * DM];
__device__ __nv_bfloat16 g_q_lo[MROWS * DM];
__device__ __nv_bfloat16 g_k_hi[MROWS * DM];
__device__ __nv_bfloat16 g_k_lo[MROWS * DM];
__device__ __nv_bfloat16 g_v_hi[MROWS * DM];
__device__ __nv_bfloat16 g_v_lo[MROWS * DM];
__device__ __nv_bfloat16 g_a_hi[MROWS * DM];
__device__ __nv_bfloat16 g_a_lo[MROWS * DM];

// ---------------------------------------------------------------------------
// PTX helpers
// ---------------------------------------------------------------------------
__device__ __forceinline__ uint32_t smem_u32(const void* p) {
    uint32_t a;
    asm("{ .reg .u64 t; cvta.to.shared.u64 t, %1; cvt.u32.u64 %0, t; }"
        : "=r"(a) : "l"(p));
    return a;
}

__device__ __forceinline__ void ldmat_x4(uint32_t* r, uint32_t addr) {
    asm volatile("ldmatrix.sync.aligned.m8n8.x4.shared.b16 {%0,%1,%2,%3}, [%4];"
                 : "=r"(r[0]), "=r"(r[1]), "=r"(r[2]), "=r"(r[3]) : "r"(addr));
}
__device__ __forceinline__ void ldmat_x4_t(uint32_t* r, uint32_t addr) {
    asm volatile("ldmatrix.sync.aligned.m8n8.x4.trans.shared.b16 {%0,%1,%2,%3}, [%4];"
                 : "=r"(r[0]), "=r"(r[1]), "=r"(r[2]), "=r"(r[3]) : "r"(addr));
}

__device__ __forceinline__ void mma_bf16(float* c, const uint32_t* a, const uint32_t* b) {
    asm volatile(
        "mma.sync.aligned.m16n8k16.row.col.f32.bf16.bf16.f32 "
        "{%0,%1,%2,%3}, {%4,%5,%6,%7}, {%8,%9}, {%0,%1,%2,%3};"
        : "+f"(c[0]), "+f"(c[1]), "+f"(c[2]), "+f"(c[3])
        : "r"(a[0]), "r"(a[1]), "r"(a[2]), "r"(a[3]), "r"(b[0]), "r"(b[1]));
}

__device__ __forceinline__ void cp16(uint32_t dst, const void* src) {
    asm volatile("cp.async.cg.shared.global [%0], [%1], 16;" :: "r"(dst), "l"(src));
}
__device__ __forceinline__ void cp_commit() {
    asm volatile("cp.async.commit_group;");
}
template <int N> __device__ __forceinline__ void cp_wait() {
    asm volatile("cp.async.wait_group %0;" :: "n"(N));
}

__device__ __forceinline__ uint32_t pack_bf2(float lo, float hi) {
    __nv_bfloat162 v = __floats2bfloat162_rn(lo, hi);
    return *reinterpret_cast<uint32_t*>(&v);
}

// ---------------------------------------------------------------------------
// Fused split fp32 -> (hi, lo) bf16 : x AND the four weight matrices
// ---------------------------------------------------------------------------
__device__ __forceinline__ void split4(const float4 v, uint2& ho, uint2& lo2) {
    float f[4] = {v.x, v.y, v.z, v.w};
    __nv_bfloat16 h[4], l[4];
#pragma unroll
    for (int j = 0; j < 4; j++) {
        h[j] = __float2bfloat16(f[j]);
        l[j] = __float2bfloat16(f[j] - __bfloat162float(h[j]));
    }
    ho = *(uint2*)h;
    lo2 = *(uint2*)l;
}

__global__ __launch_bounds__(256) void split_all_kernel(
    const float* __restrict__ x,
    const float* __restrict__ w0, const float* __restrict__ w1,
    const float* __restrict__ w2, const float* __restrict__ w3)
{
    constexpr int NX4 = MROWS * DM / 4;   // 1,048,576
    constexpr int NW4 = DM * DM / 4;      // 262,144
    int i = blockIdx.x * blockDim.x + threadIdx.x;
    if (i < NX4) {
        uint2 h, l;
        split4(((const float4*)x)[i], h, l);
        ((uint2*)g_x_hi)[i] = h;
        ((uint2*)g_x_lo)[i] = l;
    } else {
        int j = i - NX4;
        int m = j >> 18;
        int r = j & (NW4 - 1);
        const float* src = (m == 0) ? w0 : (m == 1) ? w1 : (m == 2) ? w2 : w3;
        uint2 h, l;
        split4(((const float4*)src)[r], h, l);
        ((uint2*)g_w_hi)[(size_t)m * NW4 + r] = h;
        ((uint2*)g_w_lo)[(size_t)m * NW4 + r] = l;
    }
}

// ---------------------------------------------------------------------------
// mma.sync split-bf16 NT GEMM: CTA tile 128(M) x 256(N), 256 threads,
// 8 warps as 2x4 of 64x64 tiles, BK=32, 3-stage cp.async pipeline, 1 CTA/SM.
// ---------------------------------------------------------------------------
constexpr int BK = 32;
constexpr int NCH = DM / BK;                   // 32
constexpr int RS = 40;                         // row stride in bf16 elems (80 B)
constexpr uint32_t TILE_A = 128 * 80;          // 10240 per A tensor
constexpr uint32_t TILE_Bt = 256 * 80;         // 20480 per B tensor
constexpr uint32_t STAGE_B = 2 * TILE_A + 2 * TILE_Bt;   // 61440
constexpr uint32_t GEMM_SMEM = 3 * STAGE_B;    // 184320

__device__ __forceinline__ void gemm_body(
    const __nv_bfloat16* __restrict__ Ahi,
    const __nv_bfloat16* __restrict__ Alo,
    const __nv_bfloat16* __restrict__ Bhi,
    const __nv_bfloat16* __restrict__ Blo,
    float* __restrict__ C,
    __nv_bfloat16* __restrict__ outHi,
    __nv_bfloat16* __restrict__ outLo,
    float scale, uint32_t sb, int row0, int col0)
{
    const int tid = threadIdx.x, lane = tid & 31, wid = tid >> 5;
    const int wr = wid & 1, wc = wid >> 1;        // 2x4 warp grid of 64x64
    const int m0w = wr * 64, n0w = wc * 64;

    float acc[4][8][4];
#pragma unroll
    for (int mi = 0; mi < 4; mi++)
#pragma unroll
        for (int ni = 0; ni < 8; ni++)
#pragma unroll
            for (int j = 0; j < 4; j++) acc[mi][ni][j] = 0.f;

    // per chunk: A hi/lo 128x32 (1024 cp16) + B hi/lo 256x32 (2048) = 3072
    auto load_chunk = [&](int c, int stage) {
        const int k0 = c * BK;
        const uint32_t stg = sb + (uint32_t)stage * STAGE_B;
#pragma unroll
        for (int j = 0; j < 12; j++) {
            int idx = tid + j * 256;               // 0..3071
            if (idx < 1024) {
                int t = idx >> 9, r = (idx & 511) >> 2, c16 = idx & 3;
                const __nv_bfloat16* s = t ? Alo : Ahi;
                cp16(stg + (uint32_t)t * TILE_A + (uint32_t)(r * 80 + c16 * 16),
                     s + (size_t)(row0 + r) * DM + k0 + c16 * 8);
            } else {
                int i2 = idx - 1024;               // 0..2047
                int t = i2 >> 10, r = (i2 & 1023) >> 2, c16 = i2 & 3;
                const __nv_bfloat16* s = t ? Blo : Bhi;
                cp16(stg + 2 * TILE_A + (uint32_t)t * TILE_Bt
                         + (uint32_t)(r * 80 + c16 * 16),
                     s + (size_t)(col0 + r) * DM + k0 + c16 * 8);
            }
        }
        cp_commit();
    };

    load_chunk(0, 0);
    load_chunk(1, 1);

    for (int c = 0; c < NCH; c++) {
        if (c + 2 < NCH) { load_chunk(c + 2, (c + 2) % 3); cp_wait<2>(); }
        else if (c + 1 < NCH) { cp_wait<1>(); }
        else { cp_wait<0>(); }
        __syncthreads();

        const uint32_t stg = sb + (uint32_t)(c % 3) * STAGE_B;
        const uint32_t uAh = stg, uAl = stg + TILE_A;
        const uint32_t uBh = stg + 2 * TILE_A, uBl = uBh + TILE_Bt;

        const int arow = m0w + (lane & 15);
        const int brow = n0w + (lane & 7) + ((lane >> 4) << 3);

#pragma unroll
        for (int kt = 0; kt < 2; kt++) {
            const int acol = kt * 16 + ((lane >> 4) << 3);
            const int bcol = kt * 16 + (((lane >> 3) & 1) << 3);
            uint32_t a_hi[4][4], a_lo[4][4];
#pragma unroll
            for (int mi = 0; mi < 4; mi++) {
                uint32_t off = (uint32_t)(((arow + mi * 16) * RS + acol) * 2);
                ldmat_x4(a_hi[mi], uAh + off);
                ldmat_x4(a_lo[mi], uAl + off);
            }
#pragma unroll
            for (int p = 0; p < 4; p++) {
                uint32_t off = (uint32_t)(((brow + p * 16) * RS + bcol) * 2);
                uint32_t r4[4], s4[4];
                ldmat_x4(r4, uBh + off);
                ldmat_x4(s4, uBl + off);
                uint32_t bh0[2] = {r4[0], r4[1]}, bh1[2] = {r4[2], r4[3]};
                uint32_t bl0[2] = {s4[0], s4[1]}, bl1[2] = {s4[2], s4[3]};
#pragma unroll
                for (int mi = 0; mi < 4; mi++) {
                    mma_bf16(acc[mi][2 * p],     a_hi[mi], bh0);
                    mma_bf16(acc[mi][2 * p + 1], a_hi[mi], bh1);
                    mma_bf16(acc[mi][2 * p],     a_lo[mi], bh0);
                    mma_bf16(acc[mi][2 * p + 1], a_lo[mi], bh1);
                    mma_bf16(acc[mi][2 * p],     a_hi[mi], bl0);
                    mma_bf16(acc[mi][2 * p + 1], a_hi[mi], bl1);
                }
            }
        }
        __syncthreads();
    }

    const int g = lane >> 2, tg = lane & 3;
    if (outHi) {
#pragma unroll
        for (int mi = 0; mi < 4; mi++) {
#pragma unroll
            for (int ni = 0; ni < 8; ni++) {
                int rgl = row0 + m0w + mi * 16 + g;
                int cgl = col0 + n0w + ni * 8 + tg * 2;
#pragma unroll
                for (int half = 0; half < 2; half++) {
                    float v0 = acc[mi][ni][2 * half + 0] * scale;
                    float v1 = acc[mi][ni][2 * half + 1] * scale;
                    __nv_bfloat16 h0 = __float2bfloat16(v0);
                    __nv_bfloat16 h1 = __float2bfloat16(v1);
                    __nv_bfloat162 hv; hv.x = h0; hv.y = h1;
                    __nv_bfloat162 lv;
                    lv.x = __float2bfloat16(v0 - __bfloat162float(h0));
                    lv.y = __float2bfloat16(v1 - __bfloat162float(h1));
                    size_t off = (size_t)(rgl + 8 * half) * DM + cgl;
                    *(__nv_bfloat162*)&outHi[off] = hv;
                    *(__nv_bfloat162*)&outLo[off] = lv;
                }
            }
        }
    } else {
#pragma unroll
        for (int mi = 0; mi < 4; mi++) {
#pragma unroll
            for (int ni = 0; ni < 8; ni++) {
                int rgl = row0 + m0w + mi * 16 + g;
                int cgl = col0 + n0w + ni * 8 + tg * 2;
                *(float2*)&C[(size_t)rgl * DM + cgl] =
                    make_float2(acc[mi][ni][0], acc[mi][ni][1]);
                *(float2*)&C[(size_t)(rgl + 8) * DM + cgl] =
                    make_float2(acc[mi][ni][2], acc[mi][ni][3]);
            }
        }
    }
}

__global__ __launch_bounds__(256, 1)
void qkv_fused_kernel()
{
    extern __shared__ __align__(128) char smem[];
    const uint32_t sb = smem_u32(smem);
    const int z = blockIdx.z;
    const __nv_bfloat16* wh = g_w_hi + (size_t)z * DM * DM;
    const __nv_bfloat16* wl = g_w_lo + (size_t)z * DM * DM;
    __nv_bfloat16* oh = (z == 0) ? g_q_hi : (z == 1) ? g_k_hi : g_v_hi;
    __nv_bfloat16* ol = (z == 0) ? g_q_lo : (z == 1) ? g_k_lo : g_v_lo;
    float scale = (z == 0) ? 0.125f : 1.0f;
    gemm_body(g_x_hi, g_x_lo, wh, wl, nullptr, oh, ol, scale, sb,
              blockIdx.y * 128, blockIdx.x * 256);
}

__global__ __launch_bounds__(256, 1)
void oproj_kernel(float* __restrict__ out)
{
    extern __shared__ __align__(128) char smem[];
    const uint32_t sb = smem_u32(smem);
    gemm_body(g_a_hi, g_a_lo, g_w_hi + (size_t)3 * DM * DM, g_w_lo + (size_t)3 * DM * DM,
              out, nullptr, nullptr, 1.0f, sb, blockIdx.y * 128, blockIdx.x * 256);
}

// ---------------------------------------------------------------------------
// Tensor-core flash attention: 256 threads, 8 warps x 32 query rows
// (two 16-row subtiles), CTA = 256 queries, key blocks of 64, 1 CTA/SM.
// ---------------------------------------------------------------------------
constexpr uint32_t QT   = 256 * 144;           // 36864 per Q tensor
constexpr uint32_t QREG = 2 * QT;              // 73728
constexpr uint32_t KVT  = 64 * 144;            // 9216 per KV tensor
constexpr uint32_t STG  = 4 * KVT;             // 36864 per stage
constexpr uint32_t ATTN_SMEM = QREG + 2 * STG; // 147456

__global__ __launch_bounds__(256, 1)
void attn_mma_kernel(const unsigned char* __restrict__ pad)
{
    extern __shared__ __align__(128) char dsm[];
    __shared__ float pmadd[2][64];
    const uint32_t sb = smem_u32(dsm);
    const int tid = threadIdx.x, lane = tid & 31, w = tid >> 5;
    const int qb = gridDim.x - 1 - blockIdx.x;   // heavy tiles first
    const int bh = blockIdx.y, b = bh >> 4, h = bh & 15;
    const int qw0 = w * 32;                      // warp's 32 query rows
    const int qt0 = qb * 256;
    const int g = lane >> 2, tg = lane & 3;

    // ---- Load Q tile (hi/lo, 256 rows) ----
    {
        const __nv_bfloat16* qs[2] = {g_q_hi, g_q_lo};
#pragma unroll
        for (int j = 0; j < 16; j++) {
            int idx = tid + j * 256;
            int t = idx >> 11, r = (idx & 2047) >> 3, c16 = idx & 7;
            const __nv_bfloat16* src =
                qs[t] + (size_t)(b * Tt + qt0 + r) * DM + h * HD + c16 * 8;
            cp16(sb + (uint32_t)(t * (int)QT + r * 144 + c16 * 16), src);
        }
        cp_commit();
    }

    auto load_kv = [&](int kb2, int st) {
        const __nv_bfloat16* srcs[4] = {g_k_hi, g_k_lo, g_v_hi, g_v_lo};
#pragma unroll
        for (int j = 0; j < 8; j++) {
            int idx = tid + j * 256;
            int t = idx >> 9, r = (idx & 511) >> 3, c16 = idx & 7;
            const __nv_bfloat16* src =
                srcs[t] + (size_t)(b * Tt + kb2 * 64 + r) * DM + h * HD + c16 * 8;
            cp16(sb + QREG + (uint32_t)(st * (int)STG + t * (int)KVT + r * 144 + c16 * 16), src);
        }
        if (tid < 64)
            pmadd[st][tid] = pad[b * Tt + kb2 * 64 + tid] ? -INFINITY : 0.f;
        cp_commit();
    };

    float m[2][2], l[2][2];
#pragma unroll
    for (int mi = 0; mi < 2; mi++) {
        m[mi][0] = -INFINITY; m[mi][1] = -INFINITY;
        l[mi][0] = 0.f; l[mi][1] = 0.f;
    }
    float oacc[2][8][4];
#pragma unroll
    for (int mi = 0; mi < 2; mi++)
#pragma unroll
        for (int j = 0; j < 8; j++)
#pragma unroll
            for (int cc = 0; cc < 4; cc++) oacc[mi][j][cc] = 0.f;

    const int nkb = 4 * qb + 4;
    load_kv(0, 0);

    for (int kb = 0; kb < nkb; kb++) {
        if (kb + 1 < nkb) { load_kv(kb + 1, (kb + 1) & 1); cp_wait<1>(); }
        else              { cp_wait<0>(); }
        __syncthreads();

        const uint32_t st = sb + QREG + (uint32_t)(kb & 1) * STG;
        const int kg0 = kb * 64;

        if (kg0 <= qt0 + qw0 + 31) {
            // ---- S = Q K^T ----
            float sacc[2][8][4];
#pragma unroll
            for (int mi = 0; mi < 2; mi++)
#pragma unroll
                for (int j = 0; j < 8; j++)
#pragma unroll
                    for (int cc = 0; cc < 4; cc++) sacc[mi][j][cc] = 0.f;

            const int brow = (lane & 7) + ((lane >> 4) << 3);
#pragma unroll
            for (int kt = 0; kt < 4; kt++) {
                uint32_t qh4[2][4], ql4[2][4];
#pragma unroll
                for (int mi = 0; mi < 2; mi++) {
                    uint32_t off = (uint32_t)((qw0 + mi * 16 + (lane & 15)) * 144
                                              + kt * 32 + ((lane >> 4) << 4));
                    ldmat_x4(qh4[mi], sb + off);
                    ldmat_x4(ql4[mi], sb + QT + off);
                }
                const int bcol = kt * 16 + (((lane >> 3) & 1) << 3);
#pragma unroll
                for (int p = 0; p < 4; p++) {
                    uint32_t off = (uint32_t)((brow + p * 16) * 144 + bcol * 2);
                    uint32_t r4[4], s4[4];
                    ldmat_x4(r4, st + off);
                    ldmat_x4(s4, st + KVT + off);
                    uint32_t bh0[2] = {r4[0], r4[1]}, bh1[2] = {r4[2], r4[3]};
                    uint32_t bl0[2] = {s4[0], s4[1]}, bl1[2] = {s4[2], s4[3]};
#pragma unroll
                    for (int mi = 0; mi < 2; mi++) {
                        mma_bf16(sacc[mi][2 * p],     qh4[mi], bh0);
                        mma_bf16(sacc[mi][2 * p + 1], qh4[mi], bh1);
                        mma_bf16(sacc[mi][2 * p],     ql4[mi], bh0);
                        mma_bf16(sacc[mi][2 * p + 1], ql4[mi], bh1);
                        mma_bf16(sacc[mi][2 * p],     qh4[mi], bl0);
                        mma_bf16(sacc[mi][2 * p + 1], qh4[mi], bl1);
                    }
                }
            }

            // ---- mask + padding + softmax per m-subtile ----
#pragma unroll
            for (int mi = 0; mi < 2; mi++) {
                const int qrow0 = qt0 + qw0 + mi * 16;
                const bool needmask = (kg0 + 63 > qrow0);
                const int qg0r = qrow0 + g;
                const int qg1r = qg0r + 8;
#pragma unroll
                for (int j = 0; j < 8; j++) {
                    int lc = j * 8 + tg * 2;
                    float pm0 = pmadd[kb & 1][lc];
                    float pm1 = pmadd[kb & 1][lc + 1];
                    sacc[mi][j][0] += pm0; sacc[mi][j][1] += pm1;
                    sacc[mi][j][2] += pm0; sacc[mi][j][3] += pm1;
                    if (needmask) {
                        int c0 = kg0 + lc;
                        if (c0     > qg0r) sacc[mi][j][0] = -INFINITY;
                        if (c0 + 1 > qg0r) sacc[mi][j][1] = -INFINITY;
                        if (c0     > qg1r) sacc[mi][j][2] = -INFINITY;
                        if (c0 + 1 > qg1r) sacc[mi][j][3] = -INFINITY;
                    }
                }

                float mx0 = -INFINITY, mx1 = -INFINITY;
#pragma unroll
                for (int j = 0; j < 8; j++) {
                    mx0 = fmaxf(mx0, fmaxf(sacc[mi][j][0], sacc[mi][j][1]));
                    mx1 = fmaxf(mx1, fmaxf(sacc[mi][j][2], sacc[mi][j][3]));
                }
                mx0 = fmaxf(mx0, __shfl_xor_sync(0xffffffffu, mx0, 1));
                mx0 = fmaxf(mx0, __shfl_xor_sync(0xffffffffu, mx0, 2));
                mx1 = fmaxf(mx1, __shfl_xor_sync(0xffffffffu, mx1, 1));
                mx1 = fmaxf(mx1, __shfl_xor_sync(0xffffffffu, mx1, 2));

                float m0n = fmaxf(m[mi][0], mx0), m1n = fmaxf(m[mi][1], mx1);
                float a0 = __expf(m[mi][0] - m0n), a1 = __expf(m[mi][1] - m1n);

                float s0 = 0.f, s1 = 0.f;
#pragma unroll
                for (int j = 0; j < 8; j++) {
                    sacc[mi][j][0] = __expf(sacc[mi][j][0] - m0n);
                    sacc[mi][j][1] = __expf(sacc[mi][j][1] - m0n);
                    sacc[mi][j][2] = __expf(sacc[mi][j][2] - m1n);
                    sacc[mi][j][3] = __expf(sacc[mi][j][3] - m1n);
                    s0 += sacc[mi][j][0] + sacc[mi][j][1];
                    s1 += sacc[mi][j][2] + sacc[mi][j][3];
                }
                s0 += __shfl_xor_sync(0xffffffffu, s0, 1);
                s0 += __shfl_xor_sync(0xffffffffu, s0, 2);
                s1 += __shfl_xor_sync(0xffffffffu, s1, 1);
                s1 += __shfl_xor_sync(0xffffffffu, s1, 2);

                l[mi][0] = l[mi][0] * a0 + s0;
                l[mi][1] = l[mi][1] * a1 + s1;
                m[mi][0] = m0n; m[mi][1] = m1n;
#pragma unroll
                for (int j = 0; j < 8; j++) {
                    oacc[mi][j][0] *= a0; oacc[mi][j][1] *= a0;
                    oacc[mi][j][2] *= a1; oacc[mi][j][3] *= a1;
                }
            }

            // ---- O += P V ----
            const uint32_t vb = st + 2 * KVT;
#pragma unroll
            for (int kt = 0; kt < 4; kt++) {
                // build P frags for this kt per m-subtile
                uint32_t ph[2][4], pl[2][4];
#pragma unroll
                for (int mi = 0; mi < 2; mi++) {
#pragma unroll
                    for (int hf = 0; hf < 2; hf++) {
                        const float* s = sacc[mi][2 * kt + hf];
                        float f0 = s[0], f1 = s[1], f2 = s[2], f3 = s[3];
                        __nv_bfloat16 h0 = __float2bfloat16(f0);
                        __nv_bfloat16 h1 = __float2bfloat16(f1);
                        __nv_bfloat16 h2 = __float2bfloat16(f2);
                        __nv_bfloat16 h3 = __float2bfloat16(f3);
                        ph[mi][2 * hf + 0] = pack_bf2(__bfloat162float(h0), __bfloat162float(h1));
                        ph[mi][2 * hf + 1] = pack_bf2(__bfloat162float(h2), __bfloat162float(h3));
                        pl[mi][2 * hf + 0] = pack_bf2(f0 - __bfloat162float(h0),
                                                      f1 - __bfloat162float(h1));
                        pl[mi][2 * hf + 1] = pack_bf2(f2 - __bfloat162float(h2),
                                                      f3 - __bfloat162float(h3));
                    }
                }
                const int vrow = kt * 16 + (lane & 15);
#pragma unroll
                for (int p = 0; p < 4; p++) {
                    uint32_t off = (uint32_t)(vrow * 144 + (p * 16 + ((lane >> 4) << 3)) * 2);
                    uint32_t r4[4], s4[4];
                    ldmat_x4_t(r4, vb + off);
                    ldmat_x4_t(s4, vb + KVT + off);
                    uint32_t vh0[2] = {r4[0], r4[1]}, vh1[2] = {r4[2], r4[3]};
                    uint32_t vl0[2] = {s4[0], s4[1]}, vl1[2] = {s4[2], s4[3]};
#pragma unroll
                    for (int mi = 0; mi < 2; mi++) {
                        mma_bf16(oacc[mi][2 * p],     ph[mi], vh0);
                        mma_bf16(oacc[mi][2 * p + 1], ph[mi], vh1);
                        mma_bf16(oacc[mi][2 * p],     pl[mi], vh0);
                        mma_bf16(oacc[mi][2 * p + 1], pl[mi], vh1);
                        mma_bf16(oacc[mi][2 * p],     ph[mi], vl0);
                        mma_bf16(oacc[mi][2 * p + 1], ph[mi], vl1);
                    }
                }
            }
        }
        __syncthreads();
    }

    // ---- epilogue ----
#pragma unroll
    for (int mi = 0; mi < 2; mi++) {
        float inv0 = 1.f / l[mi][0], inv1 = 1.f / l[mi][1];
        const int row0 = b * Tt + qt0 + qw0 + mi * 16 + g;
#pragma unroll
        for (int j = 0; j < 8; j++) {
            int col = h * HD + j * 8 + tg * 2;
            float o0 = oacc[mi][j][0] * inv0, o1 = oacc[mi][j][1] * inv0;
            float o2 = oacc[mi][j][2] * inv1, o3 = oacc[mi][j][3] * inv1;
            __nv_bfloat16 h0 = __float2bfloat16(o0), h1 = __float2bfloat16(o1);
            __nv_bfloat16 h2 = __float2bfloat16(o2), h3 = __float2bfloat16(o3);
            __nv_bfloat162 hv0; hv0.x = h0; hv0.y = h1;
            __nv_bfloat162 lv0;
            lv0.x = __float2bfloat16(o0 - __bfloat162float(h0));
            lv0.y = __float2bfloat16(o1 - __bfloat162float(h1));
            __nv_bfloat162 hv1; hv1.x = h2; hv1.y = h3;
            __nv_bfloat162 lv1;
            lv1.x = __float2bfloat16(o2 - __bfloat162float(h2));
            lv1.y = __float2bfloat16(o3 - __bfloat162float(h3));
            *(__nv_bfloat162*)&g_a_hi[(size_t)row0 * DM + col] = hv0;
            *(__nv_bfloat162*)&g_a_lo[(size_t)row0 * DM + col] = lv0;
            *(__nv_bfloat162*)&g_a_hi[(size_t)(row0 + 8) * DM + col] = hv1;
            *(__nv_bfloat162*)&g_a_lo[(size_t)(row0 + 8) * DM + col] = lv1;
        }
    }
}

// ---------------------------------------------------------------------------
// Launch
// ---------------------------------------------------------------------------
extern "C" void kernel_launch(void* const* d_in, const int* in_sizes, int n_in,
                              void* d_out, int out_size)
{
    const float* x  = (const float*)d_in[0];
    const unsigned char* pad = (const unsigned char*)d_in[1];
    const float* Wq = (const float*)d_in[2];
    const float* Wk = (const float*)d_in[3];
    const float* Wv = (const float*)d_in[4];
    const float* Wo = (const float*)d_in[5];
    float* out = (float*)d_out;

    cudaFuncSetAttribute(qkv_fused_kernel,
                         cudaFuncAttributeMaxDynamicSharedMemorySize, GEMM_SMEM);
    cudaFuncSetAttribute(oproj_kernel,
                         cudaFuncAttributeMaxDynamicSharedMemorySize, GEMM_SMEM);
    cudaFuncSetAttribute(attn_mma_kernel,
                         cudaFuncAttributeMaxDynamicSharedMemorySize, ATTN_SMEM);

    split_all_kernel<<<8192, 256>>>(x, Wq, Wk, Wv, Wo);

    dim3 gg(DM / 256, MROWS / 128, 3);     // 4 x 32 x 3
    qkv_fused_kernel<<<gg, 256, GEMM_SMEM>>>();

    dim3 attn_grid(Tt / 256, Bb * Hh);     // 8 x 32
    attn_mma_kernel<<<attn_grid, 256, ATTN_SMEM>>>(pad);

    dim3 og(DM / 256, MROWS / 128);        // 4 x 32
    oproj_kernel<<<og, 256, GEMM_SMEM>>>(out);
}

// round 12
// speedup vs baseline: 1.0687x; 1.0687x over previous
#include <cuda_runtime.h>
#include <cuda_bf16.h>
#include <cstdint>

// Problem constants
constexpr int Bb = 2;
constexpr int Tt = 2048;
constexpr int DM = 1024;
constexpr int Hh = 16;
constexpr int HD = 64;
constexpr int MROWS = Bb * Tt;   // 4096

// Scratch (no allocation allowed -> __device__ globals)
__device__ __nv_bfloat16 g_x_hi[MROWS * DM];
__device__ __nv_bfloat16 g_x_lo[MROWS * DM];
__device__ __nv_bfloat16 g_w_hi[4 * DM * DM];   // Wq, Wk, Wv, Wo
__device__ __nv_bfloat16 g_w_lo[4 * DM * DM];
__device__ __nv_bfloat16 g_q_hi[MROWS * DM];
__device__ __nv_bfloat16 g_q_lo[MROWS * DM];
__device__ __nv_bfloat16 g_k_hi[MROWS * DM];
__device__ __nv_bfloat16 g_k_lo[MROWS * DM];
__device__ __nv_bfloat16 g_v_hi[MROWS * DM];
__device__ __nv_bfloat16 g_v_lo[MROWS * DM];
__device__ __nv_bfloat16 g_a_hi[MROWS * DM];
__device__ __nv_bfloat16 g_a_lo[MROWS * DM];

// ---------------------------------------------------------------------------
// PTX helpers
// ---------------------------------------------------------------------------
__device__ __forceinline__ uint32_t smem_u32(const void* p) {
    uint32_t a;
    asm("{ .reg .u64 t; cvta.to.shared.u64 t, %1; cvt.u32.u64 %0, t; }"
        : "=r"(a) : "l"(p));
    return a;
}

__device__ __forceinline__ void ldmat_x4(uint32_t* r, uint32_t addr) {
    asm volatile("ldmatrix.sync.aligned.m8n8.x4.shared.b16 {%0,%1,%2,%3}, [%4];"
                 : "=r"(r[0]), "=r"(r[1]), "=r"(r[2]), "=r"(r[3]) : "r"(addr));
}
__device__ __forceinline__ void ldmat_x4_t(uint32_t* r, uint32_t addr) {
    asm volatile("ldmatrix.sync.aligned.m8n8.x4.trans.shared.b16 {%0,%1,%2,%3}, [%4];"
                 : "=r"(r[0]), "=r"(r[1]), "=r"(r[2]), "=r"(r[3]) : "r"(addr));
}

__device__ __forceinline__ void mma_bf16(float* c, const uint32_t* a, const uint32_t* b) {
    asm volatile(
        "mma.sync.aligned.m16n8k16.row.col.f32.bf16.bf16.f32 "
        "{%0,%1,%2,%3}, {%4,%5,%6,%7}, {%8,%9}, {%0,%1,%2,%3};"
        : "+f"(c[0]), "+f"(c[1]), "+f"(c[2]), "+f"(c[3])
        : "r"(a[0]), "r"(a[1]), "r"(a[2]), "r"(a[3]), "r"(b[0]), "r"(b[1]));
}

__device__ __forceinline__ void cp16(uint32_t dst, const void* src) {
    asm volatile("cp.async.cg.shared.global [%0], [%1], 16;" :: "r"(dst), "l"(src));
}
__device__ __forceinline__ void cp_commit() {
    asm volatile("cp.async.commit_group;");
}
template <int N> __device__ __forceinline__ void cp_wait() {
    asm volatile("cp.async.wait_group %0;" :: "n"(N));
}

__device__ __forceinline__ uint32_t pack_bf2(float lo, float hi) {
    __nv_bfloat162 v = __floats2bfloat162_rn(lo, hi);
    return *reinterpret_cast<uint32_t*>(&v);
}

// ---------------------------------------------------------------------------
// Fused split fp32 -> (hi, lo) bf16 : x AND the four weight matrices
// ---------------------------------------------------------------------------
__device__ __forceinline__ void split4(const float4 v, uint2& ho, uint2& lo2) {
    float f[4] = {v.x, v.y, v.z, v.w};
    __nv_bfloat16 h[4], l[4];
#pragma unroll
    for (int j = 0; j < 4; j++) {
        h[j] = __float2bfloat16(f[j]);
        l[j] = __float2bfloat16(f[j] - __bfloat162float(h[j]));
    }
    ho = *(uint2*)h;
    lo2 = *(uint2*)l;
}

__global__ __launch_bounds__(256) void split_all_kernel(
    const float* __restrict__ x,
    const float* __restrict__ w0, const float* __restrict__ w1,
    const float* __restrict__ w2, const float* __restrict__ w3)
{
    constexpr int NX4 = MROWS * DM / 4;   // 1,048,576
    constexpr int NW4 = DM * DM / 4;      // 262,144
    int i = blockIdx.x * blockDim.x + threadIdx.x;
    if (i < NX4) {
        uint2 h, l;
        split4(((const float4*)x)[i], h, l);
        ((uint2*)g_x_hi)[i] = h;
        ((uint2*)g_x_lo)[i] = l;
    } else {
        int j = i - NX4;
        int m = j >> 18;
        int r = j & (NW4 - 1);
        const float* src = (m == 0) ? w0 : (m == 1) ? w1 : (m == 2) ? w2 : w3;
        uint2 h, l;
        split4(((const float4*)src)[r], h, l);
        ((uint2*)g_w_hi)[(size_t)m * NW4 + r] = h;
        ((uint2*)g_w_lo)[(size_t)m * NW4 + r] = l;
    }
}

// ---------------------------------------------------------------------------
// mma.sync split-bf16 NT GEMM: CTA tile 128(M) x 128(N), 128 threads,
// 4 warps as 2x2 of 64x64 tiles, BK=32, double-buffered, 2 CTAs/SM.
// ---------------------------------------------------------------------------
constexpr int BK = 32;
constexpr int NCH = DM / BK;                   // 32
constexpr int RS = 40;                         // row stride in bf16 elems (80 B)
constexpr uint32_t TILE_T = 128 * 80;          // 10240 per tensor (128 rows x 32 cols)
constexpr uint32_t STAGE_B = 4 * TILE_T;       // 40960 (Ahi, Alo, Bhi, Blo)
constexpr uint32_t GEMM_SMEM = 2 * STAGE_B;    // 81920

__device__ __forceinline__ void gemm_body(
    const __nv_bfloat16* __restrict__ Ahi,
    const __nv_bfloat16* __restrict__ Alo,
    const __nv_bfloat16* __restrict__ Bhi,
    const __nv_bfloat16* __restrict__ Blo,
    float* __restrict__ C,
    __nv_bfloat16* __restrict__ outHi,
    __nv_bfloat16* __restrict__ outLo,
    float scale, uint32_t sb, int row0, int col0)
{
    const int tid = threadIdx.x, lane = tid & 31, wid = tid >> 5;
    const int wr = wid & 1, wc = wid >> 1;        // 2x2 warp grid of 64x64
    const int m0w = wr * 64, n0w = wc * 64;

    float acc[4][8][4];
#pragma unroll
    for (int mi = 0; mi < 4; mi++)
#pragma unroll
        for (int ni = 0; ni < 8; ni++)
#pragma unroll
            for (int j = 0; j < 4; j++) acc[mi][ni][j] = 0.f;

    // per chunk: 4 tensors x 128 rows x 4 c16 = 2048 cp16; 16 per thread
    auto load_chunk = [&](int c, int stage) {
        const int k0 = c * BK;
        const uint32_t stg = sb + (uint32_t)stage * STAGE_B;
#pragma unroll
        for (int j = 0; j < 16; j++) {
            int idx = tid + j * 128;               // 0..2047
            int t = idx >> 9, r = (idx & 511) >> 2, c16 = idx & 3;
            const __nv_bfloat16* s = (t == 0) ? Ahi : (t == 1) ? Alo
                                   : (t == 2) ? Bhi : Blo;
            int rb = (t < 2) ? row0 : col0;
            cp16(stg + (uint32_t)t * TILE_T + (uint32_t)(r * 80 + c16 * 16),
                 s + (size_t)(rb + r) * DM + k0 + c16 * 8);
        }
        cp_commit();
    };

    load_chunk(0, 0);

    for (int c = 0; c < NCH; c++) {
        if (c + 1 < NCH) { load_chunk(c + 1, (c + 1) & 1); cp_wait<1>(); }
        else             { cp_wait<0>(); }
        __syncthreads();

        const uint32_t stg = sb + (uint32_t)(c & 1) * STAGE_B;
        const uint32_t uAh = stg, uAl = stg + TILE_T;
        const uint32_t uBh = stg + 2 * TILE_T, uBl = stg + 3 * TILE_T;

        const int arow = m0w + (lane & 15);
        const int brow = n0w + (lane & 7) + ((lane >> 4) << 3);

#pragma unroll
        for (int kt = 0; kt < 2; kt++) {
            const int acol = kt * 16 + ((lane >> 4) << 3);
            const int bcol = kt * 16 + (((lane >> 3) & 1) << 3);
            uint32_t a_hi[4][4], a_lo[4][4];
#pragma unroll
            for (int mi = 0; mi < 4; mi++) {
                uint32_t off = (uint32_t)(((arow + mi * 16) * RS + acol) * 2);
                ldmat_x4(a_hi[mi], uAh + off);
                ldmat_x4(a_lo[mi], uAl + off);
            }
#pragma unroll
            for (int p = 0; p < 4; p++) {
                uint32_t off = (uint32_t)(((brow + p * 16) * RS + bcol) * 2);
                uint32_t r4[4], s4[4];
                ldmat_x4(r4, uBh + off);
                ldmat_x4(s4, uBl + off);
                uint32_t bh0[2] = {r4[0], r4[1]}, bh1[2] = {r4[2], r4[3]};
                uint32_t bl0[2] = {s4[0], s4[1]}, bl1[2] = {s4[2], s4[3]};
#pragma unroll
                for (int mi = 0; mi < 4; mi++) {
                    mma_bf16(acc[mi][2 * p],     a_hi[mi], bh0);
                    mma_bf16(acc[mi][2 * p + 1], a_hi[mi], bh1);
                    mma_bf16(acc[mi][2 * p],     a_lo[mi], bh0);
                    mma_bf16(acc[mi][2 * p + 1], a_lo[mi], bh1);
                    mma_bf16(acc[mi][2 * p],     a_hi[mi], bl0);
                    mma_bf16(acc[mi][2 * p + 1], a_hi[mi], bl1);
                }
            }
        }
        __syncthreads();
    }

    const int g = lane >> 2, tg = lane & 3;
    if (outHi) {
#pragma unroll
        for (int mi = 0; mi < 4; mi++) {
#pragma unroll
            for (int ni = 0; ni < 8; ni++) {
                int rgl = row0 + m0w + mi * 16 + g;
                int cgl = col0 + n0w + ni * 8 + tg * 2;
#pragma unroll
                for (int half = 0; half < 2; half++) {
                    float v0 = acc[mi][ni][2 * half + 0] * scale;
                    float v1 = acc[mi][ni][2 * half + 1] * scale;
                    __nv_bfloat16 h0 = __float2bfloat16(v0);
                    __nv_bfloat16 h1 = __float2bfloat16(v1);
                    __nv_bfloat162 hv; hv.x = h0; hv.y = h1;
                    __nv_bfloat162 lv;
                    lv.x = __float2bfloat16(v0 - __bfloat162float(h0));
                    lv.y = __float2bfloat16(v1 - __bfloat162float(h1));
                    size_t off = (size_t)(rgl + 8 * half) * DM + cgl;
                    *(__nv_bfloat162*)&outHi[off] = hv;
                    *(__nv_bfloat162*)&outLo[off] = lv;
                }
            }
        }
    } else {
#pragma unroll
        for (int mi = 0; mi < 4; mi++) {
#pragma unroll
            for (int ni = 0; ni < 8; ni++) {
                int rgl = row0 + m0w + mi * 16 + g;
                int cgl = col0 + n0w + ni * 8 + tg * 2;
                *(float2*)&C[(size_t)rgl * DM + cgl] =
                    make_float2(acc[mi][ni][0], acc[mi][ni][1]);
                *(float2*)&C[(size_t)(rgl + 8) * DM + cgl] =
                    make_float2(acc[mi][ni][2], acc[mi][ni][3]);
            }
        }
    }
}

__global__ __launch_bounds__(128, 2)
void qkv_fused_kernel()
{
    extern __shared__ __align__(128) char smem[];
    const uint32_t sb = smem_u32(smem);
    const int z = blockIdx.z;
    const __nv_bfloat16* wh = g_w_hi + (size_t)z * DM * DM;
    const __nv_bfloat16* wl = g_w_lo + (size_t)z * DM * DM;
    __nv_bfloat16* oh = (z == 0) ? g_q_hi : (z == 1) ? g_k_hi : g_v_hi;
    __nv_bfloat16* ol = (z == 0) ? g_q_lo : (z == 1) ? g_k_lo : g_v_lo;
    float scale = (z == 0) ? 0.125f : 1.0f;
    gemm_body(g_x_hi, g_x_lo, wh, wl, nullptr, oh, ol, scale, sb,
              blockIdx.y * 128, blockIdx.x * 128);
}

__global__ __launch_bounds__(128, 2)
void oproj_kernel(float* __restrict__ out)
{
    extern __shared__ __align__(128) char smem[];
    const uint32_t sb = smem_u32(smem);
    gemm_body(g_a_hi, g_a_lo, g_w_hi + (size_t)3 * DM * DM, g_w_lo + (size_t)3 * DM * DM,
              out, nullptr, nullptr, 1.0f, sb, blockIdx.y * 128, blockIdx.x * 128);
}

// ---------------------------------------------------------------------------
// Tensor-core flash attention: 128 threads, 4 warps x 32 query rows,
// CTA = 128 queries, key blocks of 64, 2 CTAs/SM.
// smem: Q 36864 + 2 stages x 36864 = 110592.
// ---------------------------------------------------------------------------
constexpr uint32_t QT   = 128 * 144;           // 18432 per Q tensor
constexpr uint32_t QREG = 2 * QT;              // 36864
constexpr uint32_t KVT  = 64 * 144;            // 9216 per KV tensor
constexpr uint32_t STG  = 4 * KVT;             // 36864 per stage
constexpr uint32_t ATTN_SMEM = QREG + 2 * STG; // 110592

__global__ __launch_bounds__(128, 2)
void attn_mma_kernel(const unsigned char* __restrict__ pad)
{
    extern __shared__ __align__(128) char dsm[];
    __shared__ float pmadd[2][64];
    const uint32_t sb = smem_u32(dsm);
    const int tid = threadIdx.x, lane = tid & 31, w = tid >> 5;
    const int qb = gridDim.x - 1 - blockIdx.x;   // heavy tiles first
    const int bh = blockIdx.y, b = bh >> 4, h = bh & 15;
    const int qw0 = w * 32;                      // warp's 32 query rows
    const int qt0 = qb * 128;
    const int g = lane >> 2, tg = lane & 3;

    // ---- Load Q tile (hi/lo, 128 rows) ----
    {
        const __nv_bfloat16* qs[2] = {g_q_hi, g_q_lo};
#pragma unroll
        for (int j = 0; j < 16; j++) {
            int idx = tid + j * 128;
            int t = idx >> 10, r = (idx & 1023) >> 3, c16 = idx & 7;
            const __nv_bfloat16* src =
                qs[t] + (size_t)(b * Tt + qt0 + r) * DM + h * HD + c16 * 8;
            cp16(sb + (uint32_t)(t * (int)QT + r * 144 + c16 * 16), src);
        }
        cp_commit();
    }

    auto load_kv = [&](int kb2, int st) {
        const __nv_bfloat16* srcs[4] = {g_k_hi, g_k_lo, g_v_hi, g_v_lo};
#pragma unroll
        for (int j = 0; j < 16; j++) {
            int idx = tid + j * 128;
            int t = idx >> 9, r = (idx & 511) >> 3, c16 = idx & 7;
            const __nv_bfloat16* src =
                srcs[t] + (size_t)(b * Tt + kb2 * 64 + r) * DM + h * HD + c16 * 8;
            cp16(sb + QREG + (uint32_t)(st * (int)STG + t * (int)KVT + r * 144 + c16 * 16), src);
        }
        if (tid < 64)
            pmadd[st][tid] = pad[b * Tt + kb2 * 64 + tid] ? -INFINITY : 0.f;
        cp_commit();
    };

    float m[2][2], l[2][2];
#pragma unroll
    for (int mi = 0; mi < 2; mi++) {
        m[mi][0] = -INFINITY; m[mi][1] = -INFINITY;
        l[mi][0] = 0.f; l[mi][1] = 0.f;
    }
    float oacc[2][8][4];
#pragma unroll
    for (int mi = 0; mi < 2; mi++)
#pragma unroll
        for (int j = 0; j < 8; j++)
#pragma unroll
            for (int cc = 0; cc < 4; cc++) oacc[mi][j][cc] = 0.f;

    const int nkb = 2 * qb + 2;
    load_kv(0, 0);

    for (int kb = 0; kb < nkb; kb++) {
        if (kb + 1 < nkb) { load_kv(kb + 1, (kb + 1) & 1); cp_wait<1>(); }
        else              { cp_wait<0>(); }
        __syncthreads();

        const uint32_t st = sb + QREG + (uint32_t)(kb & 1) * STG;
        const int kg0 = kb * 64;

        if (kg0 <= qt0 + qw0 + 31) {
            // ---- S = Q K^T ----
            float sacc[2][8][4];
#pragma unroll
            for (int mi = 0; mi < 2; mi++)
#pragma unroll
                for (int j = 0; j < 8; j++)
#pragma unroll
                    for (int cc = 0; cc < 4; cc++) sacc[mi][j][cc] = 0.f;

            const int brow = (lane & 7) + ((lane >> 4) << 3);
#pragma unroll
            for (int kt = 0; kt < 4; kt++) {
                uint32_t qh4[2][4], ql4[2][4];
#pragma unroll
                for (int mi = 0; mi < 2; mi++) {
                    uint32_t off = (uint32_t)((qw0 + mi * 16 + (lane & 15)) * 144
                                              + kt * 32 + ((lane >> 4) << 4));
                    ldmat_x4(qh4[mi], sb + off);
                    ldmat_x4(ql4[mi], sb + QT + off);
                }
                const int bcol = kt * 16 + (((lane >> 3) & 1) << 3);
#pragma unroll
                for (int p = 0; p < 4; p++) {
                    uint32_t off = (uint32_t)((brow + p * 16) * 144 + bcol * 2);
                    uint32_t r4[4], s4[4];
                    ldmat_x4(r4, st + off);
                    ldmat_x4(s4, st + KVT + off);
                    uint32_t bh0[2] = {r4[0], r4[1]}, bh1[2] = {r4[2], r4[3]};
                    uint32_t bl0[2] = {s4[0], s4[1]}, bl1[2] = {s4[2], s4[3]};
#pragma unroll
                    for (int mi = 0; mi < 2; mi++) {
                        mma_bf16(sacc[mi][2 * p],     qh4[mi], bh0);
                        mma_bf16(sacc[mi][2 * p + 1], qh4[mi], bh1);
                        mma_bf16(sacc[mi][2 * p],     ql4[mi], bh0);
                        mma_bf16(sacc[mi][2 * p + 1], ql4[mi], bh1);
                        mma_bf16(sacc[mi][2 * p],     qh4[mi], bl0);
                        mma_bf16(sacc[mi][2 * p + 1], qh4[mi], bl1);
                    }
                }
            }

            // ---- mask + padding + softmax per m-subtile ----
#pragma unroll
            for (int mi = 0; mi < 2; mi++) {
                const int qrow0 = qt0 + qw0 + mi * 16;
                const bool needmask = (kg0 + 63 > qrow0);
                const int qg0r = qrow0 + g;
                const int qg1r = qg0r + 8;
#pragma unroll
                for (int j = 0; j < 8; j++) {
                    int lc = j * 8 + tg * 2;
                    float pm0 = pmadd[kb & 1][lc];
                    float pm1 = pmadd[kb & 1][lc + 1];
                    sacc[mi][j][0] += pm0; sacc[mi][j][1] += pm1;
                    sacc[mi][j][2] += pm0; sacc[mi][j][3] += pm1;
                    if (needmask) {
                        int c0 = kg0 + lc;
                        if (c0     > qg0r) sacc[mi][j][0] = -INFINITY;
                        if (c0 + 1 > qg0r) sacc[mi][j][1] = -INFINITY;
                        if (c0     > qg1r) sacc[mi][j][2] = -INFINITY;
                        if (c0 + 1 > qg1r) sacc[mi][j][3] = -INFINITY;
                    }
                }

                float mx0 = -INFINITY, mx1 = -INFINITY;
#pragma unroll
                for (int j = 0; j < 8; j++) {
                    mx0 = fmaxf(mx0, fmaxf(sacc[mi][j][0], sacc[mi][j][1]));
                    mx1 = fmaxf(mx1, fmaxf(sacc[mi][j][2], sacc[mi][j][3]));
                }
                mx0 = fmaxf(mx0, __shfl_xor_sync(0xffffffffu, mx0, 1));
                mx0 = fmaxf(mx0, __shfl_xor_sync(0xffffffffu, mx0, 2));
                mx1 = fmaxf(mx1, __shfl_xor_sync(0xffffffffu, mx1, 1));
                mx1 = fmaxf(mx1, __shfl_xor_sync(0xffffffffu, mx1, 2));

                float m0n = fmaxf(m[mi][0], mx0), m1n = fmaxf(m[mi][1], mx1);
                float a0 = __expf(m[mi][0] - m0n), a1 = __expf(m[mi][1] - m1n);

                float s0 = 0.f, s1 = 0.f;
#pragma unroll
                for (int j = 0; j < 8; j++) {
                    sacc[mi][j][0] = __expf(sacc[mi][j][0] - m0n);
                    sacc[mi][j][1] = __expf(sacc[mi][j][1] - m0n);
                    sacc[mi][j][2] = __expf(sacc[mi][j][2] - m1n);
                    sacc[mi][j][3] = __expf(sacc[mi][j][3] - m1n);
                    s0 += sacc[mi][j][0] + sacc[mi][j][1];
                    s1 += sacc[mi][j][2] + sacc[mi][j][3];
                }
                s0 += __shfl_xor_sync(0xffffffffu, s0, 1);
                s0 += __shfl_xor_sync(0xffffffffu, s0, 2);
                s1 += __shfl_xor_sync(0xffffffffu, s1, 1);
                s1 += __shfl_xor_sync(0xffffffffu, s1, 2);

                l[mi][0] = l[mi][0] * a0 + s0;
                l[mi][1] = l[mi][1] * a1 + s1;
                m[mi][0] = m0n; m[mi][1] = m1n;
#pragma unroll
                for (int j = 0; j < 8; j++) {
                    oacc[mi][j][0] *= a0; oacc[mi][j][1] *= a0;
                    oacc[mi][j][2] *= a1; oacc[mi][j][3] *= a1;
                }
            }

            // ---- O += P V ----
            const uint32_t vb = st + 2 * KVT;
#pragma unroll
            for (int kt = 0; kt < 4; kt++) {
                uint32_t ph[2][4], pl[2][4];
#pragma unroll
                for (int mi = 0; mi < 2; mi++) {
#pragma unroll
                    for (int hf = 0; hf < 2; hf++) {
                        const float* s = sacc[mi][2 * kt + hf];
                        float f0 = s[0], f1 = s[1], f2 = s[2], f3 = s[3];
                        __nv_bfloat16 h0 = __float2bfloat16(f0);
                        __nv_bfloat16 h1 = __float2bfloat16(f1);
                        __nv_bfloat16 h2 = __float2bfloat16(f2);
                        __nv_bfloat16 h3 = __float2bfloat16(f3);
                        ph[mi][2 * hf + 0] = pack_bf2(__bfloat162float(h0), __bfloat162float(h1));
                        ph[mi][2 * hf + 1] = pack_bf2(__bfloat162float(h2), __bfloat162float(h3));
                        pl[mi][2 * hf + 0] = pack_bf2(f0 - __bfloat162float(h0),
                                                      f1 - __bfloat162float(h1));
                        pl[mi][2 * hf + 1] = pack_bf2(f2 - __bfloat162float(h2),
                                                      f3 - __bfloat162float(h3));
                    }
                }
                const int vrow = kt * 16 + (lane & 15);
#pragma unroll
                for (int p = 0; p < 4; p++) {
                    uint32_t off = (uint32_t)(vrow * 144 + (p * 16 + ((lane >> 4) << 3)) * 2);
                    uint32_t r4[4], s4[4];
                    ldmat_x4_t(r4, vb + off);
                    ldmat_x4_t(s4, vb + KVT + off);
                    uint32_t vh0[2] = {r4[0], r4[1]}, vh1[2] = {r4[2], r4[3]};
                    uint32_t vl0[2] = {s4[0], s4[1]}, vl1[2] = {s4[2], s4[3]};
#pragma unroll
                    for (int mi = 0; mi < 2; mi++) {
                        mma_bf16(oacc[mi][2 * p],     ph[mi], vh0);
                        mma_bf16(oacc[mi][2 * p + 1], ph[mi], vh1);
                        mma_bf16(oacc[mi][2 * p],     pl[mi], vh0);
                        mma_bf16(oacc[mi][2 * p + 1], pl[mi], vh1);
                        mma_bf16(oacc[mi][2 * p],     ph[mi], vl0);
                        mma_bf16(oacc[mi][2 * p + 1], ph[mi], vl1);
                    }
                }
            }
        }
        __syncthreads();
    }

    // ---- epilogue ----
#pragma unroll
    for (int mi = 0; mi < 2; mi++) {
        float inv0 = 1.f / l[mi][0], inv1 = 1.f / l[mi][1];
        const int row0 = b * Tt + qt0 + qw0 + mi * 16 + g;
#pragma unroll
        for (int j = 0; j < 8; j++) {
            int col = h * HD + j * 8 + tg * 2;
            float o0 = oacc[mi][j][0] * inv0, o1 = oacc[mi][j][1] * inv0;
            float o2 = oacc[mi][j][2] * inv1, o3 = oacc[mi][j][3] * inv1;
            __nv_bfloat16 h0 = __float2bfloat16(o0), h1 = __float2bfloat16(o1);
            __nv_bfloat16 h2 = __float2bfloat16(o2), h3 = __float2bfloat16(o3);
            __nv_bfloat162 hv0; hv0.x = h0; hv0.y = h1;
            __nv_bfloat162 lv0;
            lv0.x = __float2bfloat16(o0 - __bfloat162float(h0));
            lv0.y = __float2bfloat16(o1 - __bfloat162float(h1));
            __nv_bfloat162 hv1; hv1.x = h2; hv1.y = h3;
            __nv_bfloat162 lv1;
            lv1.x = __float2bfloat16(o2 - __bfloat162float(h2));
            lv1.y = __float2bfloat16(o3 - __bfloat162float(h3));
            *(__nv_bfloat162*)&g_a_hi[(size_t)row0 * DM + col] = hv0;
            *(__nv_bfloat162*)&g_a_lo[(size_t)row0 * DM + col] = lv0;
            *(__nv_bfloat162*)&g_a_hi[(size_t)(row0 + 8) * DM + col] = hv1;
            *(__nv_bfloat162*)&g_a_lo[(size_t)(row0 + 8) * DM + col] = lv1;
        }
    }
}

// ---------------------------------------------------------------------------
// Launch
// ---------------------------------------------------------------------------
extern "C" void kernel_launch(void* const* d_in, const int* in_sizes, int n_in,
                              void* d_out, int out_size)
{
    const float* x  = (const float*)d_in[0];
    const unsigned char* pad = (const unsigned char*)d_in[1];
    const float* Wq = (const float*)d_in[2];
    const float* Wk = (const float*)d_in[3];
    const float* Wv = (const float*)d_in[4];
    const float* Wo = (const float*)d_in[5];
    float* out = (float*)d_out;

    cudaFuncSetAttribute(qkv_fused_kernel,
                         cudaFuncAttributeMaxDynamicSharedMemorySize, GEMM_SMEM);
    cudaFuncSetAttribute(oproj_kernel,
                         cudaFuncAttributeMaxDynamicSharedMemorySize, GEMM_SMEM);
    cudaFuncSetAttribute(attn_mma_kernel,
                         cudaFuncAttributeMaxDynamicSharedMemorySize, ATTN_SMEM);

    split_all_kernel<<<8192, 256>>>(x, Wq, Wk, Wv, Wo);

    dim3 gg(DM / 128, MROWS / 128, 3);     // 8 x 32 x 3 = 768 CTAs
    qkv_fused_kernel<<<gg, 128, GEMM_SMEM>>>();

    dim3 attn_grid(Tt / 128, Bb * Hh);     // 16 x 32 = 512 CTAs
    attn_mma_kernel<<<attn_grid, 128, ATTN_SMEM>>>(pad);

    dim3 og(DM / 128, MROWS / 128);        // 8 x 32 = 256 CTAs
    oproj_kernel<<<og, 128, GEMM_SMEM>>>(out);
}

// round 13
// speedup vs baseline: 2.6818x; 2.5094x over previous
#include <cuda_runtime.h>
#include <cuda_fp16.h>
#include <cstdint>

// Problem constants
constexpr int Bb = 2;
constexpr int Tt = 2048;
constexpr int DM = 1024;
constexpr int Hh = 16;
constexpr int HD = 64;
constexpr int MROWS = Bb * Tt;   // 4096

// Scratch (no allocation allowed -> __device__ globals)
__device__ __half g_x[MROWS * DM];
__device__ __half g_w[4 * DM * DM];   // Wq, Wk, Wv, Wo
__device__ __half g_q[MROWS * DM];    // pre-scaled by 1/8
__device__ __half g_k[MROWS * DM];
__device__ __half g_v[MROWS * DM];
__device__ __half g_a[MROWS * DM];

// ---------------------------------------------------------------------------
// PTX helpers
// ---------------------------------------------------------------------------
__device__ __forceinline__ uint32_t smem_u32(const void* p) {
    uint32_t a;
    asm("{ .reg .u64 t; cvta.to.shared.u64 t, %1; cvt.u32.u64 %0, t; }"
        : "=r"(a) : "l"(p));
    return a;
}

__device__ __forceinline__ void ldmat_x4(uint32_t* r, uint32_t addr) {
    asm volatile("ldmatrix.sync.aligned.m8n8.x4.shared.b16 {%0,%1,%2,%3}, [%4];"
                 : "=r"(r[0]), "=r"(r[1]), "=r"(r[2]), "=r"(r[3]) : "r"(addr));
}
__device__ __forceinline__ void ldmat_x4_t(uint32_t* r, uint32_t addr) {
    asm volatile("ldmatrix.sync.aligned.m8n8.x4.trans.shared.b16 {%0,%1,%2,%3}, [%4];"
                 : "=r"(r[0]), "=r"(r[1]), "=r"(r[2]), "=r"(r[3]) : "r"(addr));
}

__device__ __forceinline__ void mma_f16(float* c, const uint32_t* a, const uint32_t* b) {
    asm volatile(
        "mma.sync.aligned.m16n8k16.row.col.f32.f16.f16.f32 "
        "{%0,%1,%2,%3}, {%4,%5,%6,%7}, {%8,%9}, {%0,%1,%2,%3};"
        : "+f"(c[0]), "+f"(c[1]), "+f"(c[2]), "+f"(c[3])
        : "r"(a[0]), "r"(a[1]), "r"(a[2]), "r"(a[3]), "r"(b[0]), "r"(b[1]));
}

__device__ __forceinline__ void cp16(uint32_t dst, const void* src) {
    asm volatile("cp.async.cg.shared.global [%0], [%1], 16;" :: "r"(dst), "l"(src));
}
__device__ __forceinline__ void cp_commit() {
    asm volatile("cp.async.commit_group;");
}
template <int N> __device__ __forceinline__ void cp_wait() {
    asm volatile("cp.async.wait_group %0;" :: "n"(N));
}

__device__ __forceinline__ uint32_t pack_h2(float lo, float hi) {
    __half2 v = __floats2half2_rn(lo, hi);
    return *reinterpret_cast<uint32_t*>(&v);
}

// ---------------------------------------------------------------------------
// Convert fp32 -> fp16 : x AND the four weight matrices, one launch
// ---------------------------------------------------------------------------
__device__ __forceinline__ uint2 cvt4(const float4 v) {
    __half2 a = __floats2half2_rn(v.x, v.y);
    __half2 b = __floats2half2_rn(v.z, v.w);
    uint2 r;
    r.x = *reinterpret_cast<uint32_t*>(&a);
    r.y = *reinterpret_cast<uint32_t*>(&b);
    return r;
}

__global__ __launch_bounds__(256) void convert_all_kernel(
    const float* __restrict__ x,
    const float* __restrict__ w0, const float* __restrict__ w1,
    const float* __restrict__ w2, const float* __restrict__ w3)
{
    constexpr int NX4 = MROWS * DM / 4;   // 1,048,576
    constexpr int NW4 = DM * DM / 4;      // 262,144
    int i = blockIdx.x * blockDim.x + threadIdx.x;
    if (i < NX4) {
        ((uint2*)g_x)[i] = cvt4(((const float4*)x)[i]);
    } else {
        int j = i - NX4;
        int m = j >> 18;
        int r = j & (NW4 - 1);
        const float* src = (m == 0) ? w0 : (m == 1) ? w1 : (m == 2) ? w2 : w3;
        ((uint2*)g_w)[(size_t)m * NW4 + r] = cvt4(((const float4*)src)[r]);
    }
}

// ---------------------------------------------------------------------------
// mma.sync fp16 NT GEMM: CTA tile 128x128, 128 threads,
// 4 warps as 2x2 of 64x64 tiles, BK=32, double-buffered, 2 CTAs/SM.
// ---------------------------------------------------------------------------
constexpr int BK = 32;
constexpr int NCH = DM / BK;                   // 32
constexpr int RS = 40;                         // row stride in half elems (80 B)
constexpr uint32_t TILE_T = 128 * 80;          // 10240 per tensor
constexpr uint32_t STAGE_B = 2 * TILE_T;       // 20480 (A, B)
constexpr uint32_t GEMM_SMEM = 2 * STAGE_B;    // 40960

__device__ __forceinline__ void gemm_body(
    const __half* __restrict__ A,
    const __half* __restrict__ B,
    float* __restrict__ C,
    __half* __restrict__ outH,
    float scale, uint32_t sb, int row0, int col0)
{
    const int tid = threadIdx.x, lane = tid & 31, wid = tid >> 5;
    const int wr = wid & 1, wc = wid >> 1;        // 2x2 warp grid of 64x64
    const int m0w = wr * 64, n0w = wc * 64;

    float acc[4][8][4];
#pragma unroll
    for (int mi = 0; mi < 4; mi++)
#pragma unroll
        for (int ni = 0; ni < 8; ni++)
#pragma unroll
            for (int j = 0; j < 4; j++) acc[mi][ni][j] = 0.f;

    // per chunk: 2 tensors x 128 rows x 4 c16 = 1024 cp16; 8 per thread
    auto load_chunk = [&](int c, int stage) {
        const int k0 = c * BK;
        const uint32_t stg = sb + (uint32_t)stage * STAGE_B;
#pragma unroll
        for (int j = 0; j < 8; j++) {
            int idx = tid + j * 128;               // 0..1023
            int t = idx >> 9, r = (idx & 511) >> 2, c16 = idx & 3;
            const __half* s = t ? B : A;
            int rb = t ? col0 : row0;
            cp16(stg + (uint32_t)t * TILE_T + (uint32_t)(r * 80 + c16 * 16),
                 s + (size_t)(rb + r) * DM + k0 + c16 * 8);
        }
        cp_commit();
    };

    load_chunk(0, 0);

    for (int c = 0; c < NCH; c++) {
        if (c + 1 < NCH) { load_chunk(c + 1, (c + 1) & 1); cp_wait<1>(); }
        else             { cp_wait<0>(); }
        __syncthreads();

        const uint32_t stg = sb + (uint32_t)(c & 1) * STAGE_B;
        const uint32_t uA = stg, uB = stg + TILE_T;

        const int arow = m0w + (lane & 15);
        const int brow = n0w + (lane & 7) + ((lane >> 4) << 3);

#pragma unroll
        for (int kt = 0; kt < 2; kt++) {
            const int acol = kt * 16 + ((lane >> 4) << 3);
            const int bcol = kt * 16 + (((lane >> 3) & 1) << 3);
            uint32_t a[4][4];
#pragma unroll
            for (int mi = 0; mi < 4; mi++) {
                uint32_t off = (uint32_t)(((arow + mi * 16) * RS + acol) * 2);
                ldmat_x4(a[mi], uA + off);
            }
#pragma unroll
            for (int p = 0; p < 4; p++) {
                uint32_t off = (uint32_t)(((brow + p * 16) * RS + bcol) * 2);
                uint32_t r4[4];
                ldmat_x4(r4, uB + off);
                uint32_t b0[2] = {r4[0], r4[1]}, b1[2] = {r4[2], r4[3]};
#pragma unroll
                for (int mi = 0; mi < 4; mi++) {
                    mma_f16(acc[mi][2 * p],     a[mi], b0);
                    mma_f16(acc[mi][2 * p + 1], a[mi], b1);
                }
            }
        }
        __syncthreads();
    }

    const int g = lane >> 2, tg = lane & 3;
    if (outH) {
#pragma unroll
        for (int mi = 0; mi < 4; mi++) {
#pragma unroll
            for (int ni = 0; ni < 8; ni++) {
                int rgl = row0 + m0w + mi * 16 + g;
                int cgl = col0 + n0w + ni * 8 + tg * 2;
#pragma unroll
                for (int half = 0; half < 2; half++) {
                    float v0 = acc[mi][ni][2 * half + 0] * scale;
                    float v1 = acc[mi][ni][2 * half + 1] * scale;
                    __half2 hv = __floats2half2_rn(v0, v1);
                    *(__half2*)&outH[(size_t)(rgl + 8 * half) * DM + cgl] = hv;
                }
            }
        }
    } else {
#pragma unroll
        for (int mi = 0; mi < 4; mi++) {
#pragma unroll
            for (int ni = 0; ni < 8; ni++) {
                int rgl = row0 + m0w + mi * 16 + g;
                int cgl = col0 + n0w + ni * 8 + tg * 2;
                *(float2*)&C[(size_t)rgl * DM + cgl] =
                    make_float2(acc[mi][ni][0], acc[mi][ni][1]);
                *(float2*)&C[(size_t)(rgl + 8) * DM + cgl] =
                    make_float2(acc[mi][ni][2], acc[mi][ni][3]);
            }
        }
    }
}

__global__ __launch_bounds__(128, 2)
void qkv_fused_kernel()
{
    extern __shared__ __align__(128) char smem[];
    const uint32_t sb = smem_u32(smem);
    const int z = blockIdx.z;
    const __half* w = g_w + (size_t)z * DM * DM;
    __half* oh = (z == 0) ? g_q : (z == 1) ? g_k : g_v;
    float scale = (z == 0) ? 0.125f : 1.0f;
    gemm_body(g_x, w, nullptr, oh, scale, sb,
              blockIdx.y * 128, blockIdx.x * 128);
}

__global__ __launch_bounds__(128, 2)
void oproj_kernel(float* __restrict__ out)
{
    extern __shared__ __align__(128) char smem[];
    const uint32_t sb = smem_u32(smem);
    gemm_body(g_a, g_w + (size_t)3 * DM * DM, out, nullptr, 1.0f, sb,
              blockIdx.y * 128, blockIdx.x * 128);
}

// ---------------------------------------------------------------------------
// Tensor-core flash attention (fp16): 128 threads, 4 warps x 32 query rows,
// CTA = 128 queries, key blocks of 64, double-buffered K/V, 2+ CTAs/SM.
// smem: Q 18432 + 2 stages x 18432 = 55296.
// ---------------------------------------------------------------------------
constexpr uint32_t QT   = 128 * 144;           // 18432 Q tensor
constexpr uint32_t KVT  = 64 * 144;            // 9216 per KV tensor
constexpr uint32_t STG  = 2 * KVT;             // 18432 per stage (K, V)
constexpr uint32_t ATTN_SMEM = QT + 2 * STG;   // 55296

__global__ __launch_bounds__(128, 2)
void attn_mma_kernel(const unsigned char* __restrict__ pad)
{
    extern __shared__ __align__(128) char dsm[];
    __shared__ float pmadd[2][64];
    const uint32_t sb = smem_u32(dsm);
    const int tid = threadIdx.x, lane = tid & 31, w = tid >> 5;
    const int qb = gridDim.x - 1 - blockIdx.x;   // heavy tiles first
    const int bh = blockIdx.y, b = bh >> 4, h = bh & 15;
    const int qw0 = w * 32;                      // warp's 32 query rows
    const int qt0 = qb * 128;
    const int g = lane >> 2, tg = lane & 3;

    // ---- Load Q tile (128 rows) ----
    {
#pragma unroll
        for (int j = 0; j < 8; j++) {
            int idx = tid + j * 128;
            int r = idx >> 3, c16 = idx & 7;
            const __half* src =
                g_q + (size_t)(b * Tt + qt0 + r) * DM + h * HD + c16 * 8;
            cp16(sb + (uint32_t)(r * 144 + c16 * 16), src);
        }
        cp_commit();
    }

    auto load_kv = [&](int kb2, int st) {
#pragma unroll
        for (int j = 0; j < 8; j++) {
            int idx = tid + j * 128;
            int t = idx >> 9, r = (idx & 511) >> 3, c16 = idx & 7;
            const __half* src = (t ? g_v : g_k)
                + (size_t)(b * Tt + kb2 * 64 + r) * DM + h * HD + c16 * 8;
            cp16(sb + QT + (uint32_t)(st * (int)STG + t * (int)KVT + r * 144 + c16 * 16), src);
        }
        if (tid < 64)
            pmadd[st][tid] = pad[b * Tt + kb2 * 64 + tid] ? -INFINITY : 0.f;
        cp_commit();
    };

    float m[2][2], l[2][2];
#pragma unroll
    for (int mi = 0; mi < 2; mi++) {
        m[mi][0] = -INFINITY; m[mi][1] = -INFINITY;
        l[mi][0] = 0.f; l[mi][1] = 0.f;
    }
    float oacc[2][8][4];
#pragma unroll
    for (int mi = 0; mi < 2; mi++)
#pragma unroll
        for (int j = 0; j < 8; j++)
#pragma unroll
            for (int cc = 0; cc < 4; cc++) oacc[mi][j][cc] = 0.f;

    const int nkb = 2 * qb + 2;
    load_kv(0, 0);

    for (int kb = 0; kb < nkb; kb++) {
        if (kb + 1 < nkb) { load_kv(kb + 1, (kb + 1) & 1); cp_wait<1>(); }
        else              { cp_wait<0>(); }
        __syncthreads();

        const uint32_t st = sb + QT + (uint32_t)(kb & 1) * STG;
        const int kg0 = kb * 64;

        if (kg0 <= qt0 + qw0 + 31) {
            // ---- S = Q K^T ----
            float sacc[2][8][4];
#pragma unroll
            for (int mi = 0; mi < 2; mi++)
#pragma unroll
                for (int j = 0; j < 8; j++)
#pragma unroll
                    for (int cc = 0; cc < 4; cc++) sacc[mi][j][cc] = 0.f;

            const int brow = (lane & 7) + ((lane >> 4) << 3);
#pragma unroll
            for (int kt = 0; kt < 4; kt++) {
                uint32_t q4[2][4];
#pragma unroll
                for (int mi = 0; mi < 2; mi++) {
                    uint32_t off = (uint32_t)((qw0 + mi * 16 + (lane & 15)) * 144
                                              + kt * 32 + ((lane >> 4) << 4));
                    ldmat_x4(q4[mi], sb + off);
                }
                const int bcol = kt * 16 + (((lane >> 3) & 1) << 3);
#pragma unroll
                for (int p = 0; p < 4; p++) {
                    uint32_t off = (uint32_t)((brow + p * 16) * 144 + bcol * 2);
                    uint32_t r4[4];
                    ldmat_x4(r4, st + off);
                    uint32_t b0[2] = {r4[0], r4[1]}, b1[2] = {r4[2], r4[3]};
#pragma unroll
                    for (int mi = 0; mi < 2; mi++) {
                        mma_f16(sacc[mi][2 * p],     q4[mi], b0);
                        mma_f16(sacc[mi][2 * p + 1], q4[mi], b1);
                    }
                }
            }

            // ---- mask + padding + softmax per m-subtile ----
#pragma unroll
            for (int mi = 0; mi < 2; mi++) {
                const int qrow0 = qt0 + qw0 + mi * 16;
                const bool needmask = (kg0 + 63 > qrow0);
                const int qg0r = qrow0 + g;
                const int qg1r = qg0r + 8;
#pragma unroll
                for (int j = 0; j < 8; j++) {
                    int lc = j * 8 + tg * 2;
                    float pm0 = pmadd[kb & 1][lc];
                    float pm1 = pmadd[kb & 1][lc + 1];
                    sacc[mi][j][0] += pm0; sacc[mi][j][1] += pm1;
                    sacc[mi][j][2] += pm0; sacc[mi][j][3] += pm1;
                    if (needmask) {
                        int c0 = kg0 + lc;
                        if (c0     > qg0r) sacc[mi][j][0] = -INFINITY;
                        if (c0 + 1 > qg0r) sacc[mi][j][1] = -INFINITY;
                        if (c0     > qg1r) sacc[mi][j][2] = -INFINITY;
                        if (c0 + 1 > qg1r) sacc[mi][j][3] = -INFINITY;
                    }
                }

                float mx0 = -INFINITY, mx1 = -INFINITY;
#pragma unroll
                for (int j = 0; j < 8; j++) {
                    mx0 = fmaxf(mx0, fmaxf(sacc[mi][j][0], sacc[mi][j][1]));
                    mx1 = fmaxf(mx1, fmaxf(sacc[mi][j][2], sacc[mi][j][3]));
                }
                mx0 = fmaxf(mx0, __shfl_xor_sync(0xffffffffu, mx0, 1));
                mx0 = fmaxf(mx0, __shfl_xor_sync(0xffffffffu, mx0, 2));
                mx1 = fmaxf(mx1, __shfl_xor_sync(0xffffffffu, mx1, 1));
                mx1 = fmaxf(mx1, __shfl_xor_sync(0xffffffffu, mx1, 2));

                float m0n = fmaxf(m[mi][0], mx0), m1n = fmaxf(m[mi][1], mx1);
                float a0 = __expf(m[mi][0] - m0n), a1 = __expf(m[mi][1] - m1n);

                float s0 = 0.f, s1 = 0.f;
#pragma unroll
                for (int j = 0; j < 8; j++) {
                    sacc[mi][j][0] = __expf(sacc[mi][j][0] - m0n);
                    sacc[mi][j][1] = __expf(sacc[mi][j][1] - m0n);
                    sacc[mi][j][2] = __expf(sacc[mi][j][2] - m1n);
                    sacc[mi][j][3] = __expf(sacc[mi][j][3] - m1n);
                    s0 += sacc[mi][j][0] + sacc[mi][j][1];
                    s1 += sacc[mi][j][2] + sacc[mi][j][3];
                }
                s0 += __shfl_xor_sync(0xffffffffu, s0, 1);
                s0 += __shfl_xor_sync(0xffffffffu, s0, 2);
                s1 += __shfl_xor_sync(0xffffffffu, s1, 1);
                s1 += __shfl_xor_sync(0xffffffffu, s1, 2);

                l[mi][0] = l[mi][0] * a0 + s0;
                l[mi][1] = l[mi][1] * a1 + s1;
                m[mi][0] = m0n; m[mi][1] = m1n;
#pragma unroll
                for (int j = 0; j < 8; j++) {
                    oacc[mi][j][0] *= a0; oacc[mi][j][1] *= a0;
                    oacc[mi][j][2] *= a1; oacc[mi][j][3] *= a1;
                }
            }

            // ---- O += P V ----
            const uint32_t vb = st + KVT;
#pragma unroll
            for (int kt = 0; kt < 4; kt++) {
                uint32_t ph[2][4];
#pragma unroll
                for (int mi = 0; mi < 2; mi++) {
#pragma unroll
                    for (int hf = 0; hf < 2; hf++) {
                        const float* s = sacc[mi][2 * kt + hf];
                        ph[mi][2 * hf + 0] = pack_h2(s[0], s[1]);
                        ph[mi][2 * hf + 1] = pack_h2(s[2], s[3]);
                    }
                }
                const int vrow = kt * 16 + (lane & 15);
#pragma unroll
                for (int p = 0; p < 4; p++) {
                    uint32_t off = (uint32_t)(vrow * 144 + (p * 16 + ((lane >> 4) << 3)) * 2);
                    uint32_t r4[4];
                    ldmat_x4_t(r4, vb + off);
                    uint32_t v0[2] = {r4[0], r4[1]}, v1[2] = {r4[2], r4[3]};
#pragma unroll
                    for (int mi = 0; mi < 2; mi++) {
                        mma_f16(oacc[mi][2 * p],     ph[mi], v0);
                        mma_f16(oacc[mi][2 * p + 1], ph[mi], v1);
                    }
                }
            }
        }
        __syncthreads();
    }

    // ---- epilogue: normalize, emit fp16 ----
#pragma unroll
    for (int mi = 0; mi < 2; mi++) {
        float inv0 = 1.f / l[mi][0], inv1 = 1.f / l[mi][1];
        const int row0 = b * Tt + qt0 + qw0 + mi * 16 + g;
#pragma unroll
        for (int j = 0; j < 8; j++) {
            int col = h * HD + j * 8 + tg * 2;
            __half2 hv0 = __floats2half2_rn(oacc[mi][j][0] * inv0, oacc[mi][j][1] * inv0);
            __half2 hv1 = __floats2half2_rn(oacc[mi][j][2] * inv1, oacc[mi][j][3] * inv1);
            *(__half2*)&g_a[(size_t)row0 * DM + col] = hv0;
            *(__half2*)&g_a[(size_t)(row0 + 8) * DM + col] = hv1;
        }
    }
}

// ---------------------------------------------------------------------------
// Launch
// ---------------------------------------------------------------------------
extern "C" void kernel_launch(void* const* d_in, const int* in_sizes, int n_in,
                              void* d_out, int out_size)
{
    const float* x  = (const float*)d_in[0];
    const unsigned char* pad = (const unsigned char*)d_in[1];
    const float* Wq = (const float*)d_in[2];
    const float* Wk = (const float*)d_in[3];
    const float* Wv = (const float*)d_in[4];
    const float* Wo = (const float*)d_in[5];
    float* out = (float*)d_out;

    cudaFuncSetAttribute(qkv_fused_kernel,
                         cudaFuncAttributeMaxDynamicSharedMemorySize, GEMM_SMEM);
    cudaFuncSetAttribute(oproj_kernel,
                         cudaFuncAttributeMaxDynamicSharedMemorySize, GEMM_SMEM);
    cudaFuncSetAttribute(attn_mma_kernel,
                         cudaFuncAttributeMaxDynamicSharedMemorySize, ATTN_SMEM);

    convert_all_kernel<<<8192, 256>>>(x, Wq, Wk, Wv, Wo);

    dim3 gg(DM / 128, MROWS / 128, 3);     // 8 x 32 x 3 = 768 CTAs
    qkv_fused_kernel<<<gg, 128, GEMM_SMEM>>>();

    dim3 attn_grid(Tt / 128, Bb * Hh);     // 16 x 32 = 512 CTAs
    attn_mma_kernel<<<attn_grid, 128, ATTN_SMEM>>>(pad);

    dim3 og(DM / 128, MROWS / 128);        // 8 x 32 = 256 CTAs
    oproj_kernel<<<og, 128, GEMM_SMEM>>>(out);
}